// round 4
// baseline (speedup 1.0000x reference)
#include <cuda_runtime.h>
#include <cuda_bf16.h>
#include <math.h>

#define NSAMP 64
#define TLEN  512
#define DDIM  16
#define NDIAG 1023
#define BIGL  1.0e10f
#define LOG2E 1.4426950408889634f
#define LN2   0.6931471805599453f

// Scratch: D (pre-scaled by log2e) in diagonal-major layout: g_Ddiag[n][kk][ii]
__device__ float g_Ddiag[(size_t)NSAMP * 1024 * 512];   // 134 MB
__device__ float g_res[NSAMP];

__device__ __forceinline__ float ex2f(float x){ float y; asm("ex2.approx.ftz.f32 %0, %1;" : "=f"(y) : "f"(x)); return y; }
__device__ __forceinline__ float lg2f(float x){ float y; asm("lg2.approx.ftz.f32 %0, %1;" : "=f"(y) : "f"(x)); return y; }

// ---------------------------------------------------------------------------
// Kernel A: D[n,ii,jj] = ||X[n,ii]-Z[jj]||^2 * log2e, stored DIAGONAL-major.
// 64-row tiles, 512 threads (R1 structure — known good, 64us).
// ---------------------------------------------------------------------------
__global__ void __launch_bounds__(512) compute_D_kernel(const float* __restrict__ X,
                                                        const float* __restrict__ Z)
{
    extern __shared__ float sm[];
    float* ts  = sm;                         // 64*514
    float* zsh = ts  + 64 * 514;             // 512*17
    float* z2s = zsh + 512 * 17;             // 512 (pre-scaled by LOG2E)
    float* xs  = z2s + 512;                  // 64*16

    const int n    = blockIdx.y;
    const int row0 = blockIdx.x * 64;
    const int tid  = threadIdx.x;
    const int w    = tid >> 5;
    const int lane = tid & 31;

    for (int i = tid; i < 512 * 16; i += 512)
        zsh[(i >> 4) * 17 + (i & 15)] = Z[i];
    const float* Xn = X + ((size_t)n * TLEN + row0) * DDIM;
    for (int i = tid; i < 64 * 16; i += 512)
        xs[i] = Xn[i];
    __syncthreads();

    {
        float s = 0.f;
        #pragma unroll
        for (int c = 0; c < 16; c++) { float v = zsh[tid * 17 + c]; s = fmaf(v, v, s); }
        z2s[tid] = s * LOG2E;
    }

    float xr[4][16], x2r[4];
    #pragma unroll
    for (int q = 0; q < 4; q++) {
        float s = 0.f;
        #pragma unroll
        for (int c = 0; c < 16; c++) {
            float v = xs[(w * 4 + q) * 16 + c];
            xr[q][c] = v; s = fmaf(v, v, s);
        }
        x2r[q] = s * LOG2E;
    }
    __syncthreads();

    #pragma unroll 1
    for (int t = 0; t < 16; t++) {
        const int jj = lane + 32 * t;
        float zr[16];
        #pragma unroll
        for (int c = 0; c < 16; c++) zr[c] = zsh[jj * 17 + c];
        const float z2v = z2s[jj];
        #pragma unroll
        for (int q = 0; q < 4; q++) {
            float acc = 0.f;
            #pragma unroll
            for (int c = 0; c < 16; c++) acc = fmaf(xr[q][c], zr[c], acc);
            // (x2+z2-2xz) * log2e, clamped at 0
            ts[(w * 4 + q) * 514 + jj] = fmaxf(fmaf(acc, -2.0f * LOG2E, x2r[q] + z2v), 0.0f);
        }
    }
    __syncthreads();

    const size_t base = (size_t)n * (1024 * 512);
    for (int kkoff = w; kkoff < 575; kkoff += 16) {
        const int kk   = row0 + kkoff;
        const int iilo = max(row0, kk - 511);
        const int iihi = min(row0 + 63, kk);
        for (int ii = iilo + lane; ii <= iihi; ii += 32)
            g_Ddiag[base + (size_t)kk * 512 + ii] = ts[(ii - row0) * 514 + (kk - ii)];
    }
}

// ---------------------------------------------------------------------------
// Kernel B: log2-domain soft-DTW wavefront, 2-CTA cluster per sample.
// CTA rank r owns rows [256r, 256r+256), 8 warps, barrier per diagonal.
// Cross-CTA boundary (row 255 -> row 256): 1024-slot DSMEM ring of packed
// (tag,value) u64 — producer fire-and-forget, consumer usually hits first try.
// ---------------------------------------------------------------------------
#define PF 8

__global__ void __launch_bounds__(256) __cluster_dims__(2, 1, 1) dp_kernel()
{
    __shared__ float sb[2][8];                         // in-CTA warp boundaries
    __shared__ unsigned long long mbox[1024];          // incoming boundary ring

    const int tid  = threadIdx.x;
    const int w    = tid >> 5;
    const int lane = tid & 31;
    unsigned rank;
    asm("mov.u32 %0, %%cluster_ctarank;" : "=r"(rank));
    const int n  = blockIdx.x >> 1;
    const int gi = (int)(rank << 8) + tid;             // global row

    // init mailbox tags to never-match
    #pragma unroll
    for (int i = 0; i < 4; i++) mbox[tid + 256 * i] = 0xFFFFFFFFull;
    if (tid < 16) (&sb[0][0])[tid] = BIGL;

    const unsigned lmbox = (unsigned)__cvta_generic_to_shared(mbox);
    unsigned rmbox;
    asm("mapa.shared::cluster.u32 %0, %1, %2;" : "=r"(rmbox) : "r"(lmbox), "r"(1u));

    float r_cur  = BIGL;
    float r_diag = (rank == 0 && tid == 0) ? 0.0f : BIGL;

    const float* __restrict__ Dn = g_Ddiag + (size_t)n * (1024 * 512) + gi;
    float dbuf[PF];
    #pragma unroll
    for (int i = 0; i < PF; i++) dbuf[i] = Dn[(size_t)i * 512];

    // all cluster smem init visible before any remote store
    asm volatile("barrier.cluster.arrive.aligned;" ::: "memory");
    asm volatile("barrier.cluster.wait.aligned;" ::: "memory");

    #pragma unroll 4
    for (int kk = 0; kk < NDIAG; ++kk) {
        // off-chain prework on (left, dia)
        const float pre_m = fminf(r_cur, r_diag);
        const float pre_M = fmaxf(r_cur, r_diag);
        const float pre_s = r_cur + r_diag;
        const float dplus = dbuf[kk & (PF - 1)];

        float up = __shfl_up_sync(0xffffffffu, r_cur, 1);
        if (lane == 0) {
            if (w > 0) {
                up = sb[kk & 1][w - 1];
            } else if (rank == 0 || kk == 0) {
                up = BIGL;
            } else {
                unsigned long long pk;
                const unsigned a = lmbox + (unsigned)(kk - 1) * 8u;
                do {
                    asm volatile("ld.volatile.shared.b64 %0, [%1];" : "=l"(pk) : "r"(a));
                } while ((unsigned)pk != (unsigned)(kk - 1));
                up = __uint_as_float((unsigned)(pk >> 32));
            }
        }

        const float m   = fminf(pre_m, up);
        const float Mx  = fmaxf(pre_M, up);
        const float mid = (pre_s + up) - m - Mx;
        const float s   = 1.0f + ex2f(m - mid) + ex2f(m - Mx);
        float v = (dplus + m) - lg2f(s);
        if ((unsigned)(kk - gi) >= 512u) v = BIGL;

        r_diag = up;
        r_cur  = v;
        if (lane == 31) {
            sb[(kk + 1) & 1][w] = v;
            if (rank == 0 && w == 7) {      // publish row 255 to CTA1
                unsigned long long pk =
                    ((unsigned long long)__float_as_uint(v) << 32) | (unsigned)kk;
                asm volatile("st.shared::cluster.b64 [%0], %1;"
                             :: "r"(rmbox + (unsigned)kk * 8u), "l"(pk) : "memory");
            }
        }

        if (kk + PF < NDIAG) dbuf[kk & (PF - 1)] = Dn[(size_t)(kk + PF) * 512];
        __syncthreads();
    }

    if (rank == 1 && tid == 255) g_res[n] = r_cur * LN2;   // row 511: R[T,T]

    asm volatile("barrier.cluster.arrive.aligned;" ::: "memory");
    asm volatile("barrier.cluster.wait.aligned;" ::: "memory");
}

// ---------------------------------------------------------------------------
// Kernel C: deterministic weighted reduction.
// ---------------------------------------------------------------------------
__global__ void reduce_kernel(const float* __restrict__ wts, float* __restrict__ out)
{
    __shared__ float s[64];
    const int tid = threadIdx.x;
    s[tid] = g_res[tid] * wts[tid];
    __syncthreads();
    #pragma unroll
    for (int off = 32; off > 0; off >>= 1) {
        if (tid < off) s[tid] += s[tid + off];
        __syncthreads();
    }
    if (tid == 0) out[0] = s[0];
}

// ---------------------------------------------------------------------------
extern "C" void kernel_launch(void* const* d_in, const int* in_sizes, int n_in,
                              void* d_out, int out_size)
{
    const float* X = nullptr; const float* wts = nullptr; const float* Z = nullptr;
    for (int i = 0; i < n_in; i++) {
        if      (in_sizes[i] == NSAMP)        wts = (const float*)d_in[i];
        else if (in_sizes[i] == TLEN * DDIM)  Z   = (const float*)d_in[i];
        else                                  X   = (const float*)d_in[i];
    }
    float* out = (float*)d_out;

    const int smemA = (64 * 514 + 512 * 17 + 512 + 64 * 16) * (int)sizeof(float); // 172544
    cudaFuncSetAttribute(compute_D_kernel, cudaFuncAttributeMaxDynamicSharedMemorySize, smemA);

    compute_D_kernel<<<dim3(8, NSAMP), 512, smemA>>>(X, Z);
    dp_kernel<<<2 * NSAMP, 256>>>();            // 64 clusters of 2 CTAs
    reduce_kernel<<<1, 64>>>(wts, out);
}

// round 5
// speedup vs baseline: 1.0976x; 1.0976x over previous
#include <cuda_runtime.h>
#include <cuda_bf16.h>
#include <math.h>

#define NSAMP 64
#define TLEN  512
#define DDIM  16
#define NDIAG 1023
#define BIGL  1.0e10f
#define LOG2E 1.4426950408889634f
#define LN2   0.6931471805599453f

// Scratch: D (pre-scaled by log2e) in diagonal-major layout: g_Ddiag[n][kk][ii]
__device__ float g_Ddiag[(size_t)NSAMP * 1024 * 512];   // 134 MB
__device__ float g_res[NSAMP];

__device__ __forceinline__ float ex2f(float x){ float y; asm("ex2.approx.ftz.f32 %0, %1;" : "=f"(y) : "f"(x)); return y; }
__device__ __forceinline__ float lg2f(float x){ float y; asm("lg2.approx.ftz.f32 %0, %1;" : "=f"(y) : "f"(x)); return y; }

// ---------------------------------------------------------------------------
// Kernel A: D[n,ii,jj] = ||X[n,ii]-Z[jj]||^2 * log2e, stored DIAGONAL-major.
// (unchanged from R4 — known good, ~65us)
// ---------------------------------------------------------------------------
__global__ void __launch_bounds__(512) compute_D_kernel(const float* __restrict__ X,
                                                        const float* __restrict__ Z)
{
    extern __shared__ float sm[];
    float* ts  = sm;                         // 64*514
    float* zsh = ts  + 64 * 514;             // 512*17
    float* z2s = zsh + 512 * 17;             // 512 (pre-scaled by LOG2E)
    float* xs  = z2s + 512;                  // 64*16

    const int n    = blockIdx.y;
    const int row0 = blockIdx.x * 64;
    const int tid  = threadIdx.x;
    const int w    = tid >> 5;
    const int lane = tid & 31;

    for (int i = tid; i < 512 * 16; i += 512)
        zsh[(i >> 4) * 17 + (i & 15)] = Z[i];
    const float* Xn = X + ((size_t)n * TLEN + row0) * DDIM;
    for (int i = tid; i < 64 * 16; i += 512)
        xs[i] = Xn[i];
    __syncthreads();

    {
        float s = 0.f;
        #pragma unroll
        for (int c = 0; c < 16; c++) { float v = zsh[tid * 17 + c]; s = fmaf(v, v, s); }
        z2s[tid] = s * LOG2E;
    }

    float xr[4][16], x2r[4];
    #pragma unroll
    for (int q = 0; q < 4; q++) {
        float s = 0.f;
        #pragma unroll
        for (int c = 0; c < 16; c++) {
            float v = xs[(w * 4 + q) * 16 + c];
            xr[q][c] = v; s = fmaf(v, v, s);
        }
        x2r[q] = s * LOG2E;
    }
    __syncthreads();

    #pragma unroll 1
    for (int t = 0; t < 16; t++) {
        const int jj = lane + 32 * t;
        float zr[16];
        #pragma unroll
        for (int c = 0; c < 16; c++) zr[c] = zsh[jj * 17 + c];
        const float z2v = z2s[jj];
        #pragma unroll
        for (int q = 0; q < 4; q++) {
            float acc = 0.f;
            #pragma unroll
            for (int c = 0; c < 16; c++) acc = fmaf(xr[q][c], zr[c], acc);
            ts[(w * 4 + q) * 514 + jj] = fmaxf(fmaf(acc, -2.0f * LOG2E, x2r[q] + z2v), 0.0f);
        }
    }
    __syncthreads();

    const size_t base = (size_t)n * (1024 * 512);
    for (int kkoff = w; kkoff < 575; kkoff += 16) {
        const int kk   = row0 + kkoff;
        const int iilo = max(row0, kk - 511);
        const int iihi = min(row0 + 63, kk);
        for (int ii = iilo + lane; ii <= iihi; ii += 32)
            g_Ddiag[base + (size_t)kk * 512 + ii] = ts[(ii - row0) * 514 + (kk - ii)];
    }
}

// ---------------------------------------------------------------------------
// Kernel B: log2-domain soft-DTW wavefront. 64 CTAs (1/sample), 128 threads
// (4 warps = 1/SMSP), 4 cells/thread (rows 4t..4t+3). Barrier per diagonal
// (nw=4, cheap). One shfl + one float4 D-load per thread per diagonal.
// ---------------------------------------------------------------------------
#define PF 8

__global__ void __launch_bounds__(128) dp_kernel()
{
    const int n    = blockIdx.x;
    const int tid  = threadIdx.x;
    const int w    = tid >> 5;
    const int lane = tid & 31;

    __shared__ float sb[2][4];               // lane31-cell3 boundary, ping-pong

    if (tid < 8) (&sb[0][0])[tid] = BIGL;

    // rc[c]: R on diag kk-1 for row 4t+c.  rd[c]: R on diag kk-2 for row 4t+c-1.
    float rc[4], rd[4];
    #pragma unroll
    for (int c = 0; c < 4; c++) { rc[c] = BIGL; rd[c] = BIGL; }
    if (tid == 0) rd[0] = 0.0f;              // corner R[0][0]

    const float* __restrict__ Dn = g_Ddiag + (size_t)n * (1024 * 512);
    float4 dbuf[PF];
    #pragma unroll
    for (int i = 0; i < PF; i++)
        dbuf[i] = ((const float4*)(Dn + (size_t)i * 512))[tid];

    __syncthreads();

    #pragma unroll 2
    for (int kk = 0; kk < NDIAG; ++kk) {
        const float4 d4 = dbuf[kk & (PF - 1)];
        const float dv[4] = {d4.x, d4.y, d4.z, d4.w};

        float upsh = __shfl_up_sync(0xffffffffu, rc[3], 1);
        if (lane == 0) upsh = (w ? sb[kk & 1][w - 1] : BIGL);

        const float up[4] = {upsh, rc[0], rc[1], rc[2]};

        #pragma unroll
        for (int c = 0; c < 4; c++) {
            const float a  = up[c], b = rc[c], cc = rd[c];
            const float m  = fminf(fminf(a, b), cc);
            const float Mx = fmaxf(fmaxf(a, b), cc);
            const float mid = ((a + b) + cc) - m - Mx;
            const float s  = 1.0f + ex2f(m - mid) + ex2f(m - Mx);
            float v = (dv[c] + m) - lg2f(s);
            if ((unsigned)(kk - (4 * tid + c)) >= 512u) v = BIGL;   // outside band
            rd[c] = up[c];
            rc[c] = v;
        }

        if (lane == 31) sb[(kk + 1) & 1][w] = rc[3];
        if (kk + PF < NDIAG)
            dbuf[kk & (PF - 1)] = ((const float4*)(Dn + (size_t)(kk + PF) * 512))[tid];
        __syncthreads();
    }

    if (tid == 127) g_res[n] = rc[3] * LN2;  // row 511: R[T,T], back to ln units
}

// ---------------------------------------------------------------------------
// Kernel C: deterministic weighted reduction.
// ---------------------------------------------------------------------------
__global__ void reduce_kernel(const float* __restrict__ wts, float* __restrict__ out)
{
    __shared__ float s[64];
    const int tid = threadIdx.x;
    s[tid] = g_res[tid] * wts[tid];
    __syncthreads();
    #pragma unroll
    for (int off = 32; off > 0; off >>= 1) {
        if (tid < off) s[tid] += s[tid + off];
        __syncthreads();
    }
    if (tid == 0) out[0] = s[0];
}

// ---------------------------------------------------------------------------
extern "C" void kernel_launch(void* const* d_in, const int* in_sizes, int n_in,
                              void* d_out, int out_size)
{
    const float* X = nullptr; const float* wts = nullptr; const float* Z = nullptr;
    for (int i = 0; i < n_in; i++) {
        if      (in_sizes[i] == NSAMP)        wts = (const float*)d_in[i];
        else if (in_sizes[i] == TLEN * DDIM)  Z   = (const float*)d_in[i];
        else                                  X   = (const float*)d_in[i];
    }
    float* out = (float*)d_out;

    const int smemA = (64 * 514 + 512 * 17 + 512 + 64 * 16) * (int)sizeof(float); // 172544
    cudaFuncSetAttribute(compute_D_kernel, cudaFuncAttributeMaxDynamicSharedMemorySize, smemA);

    compute_D_kernel<<<dim3(8, NSAMP), 512, smemA>>>(X, Z);
    dp_kernel<<<NSAMP, 128>>>();
    reduce_kernel<<<1, 64>>>(wts, out);
}

// round 7
// speedup vs baseline: 2.5832x; 2.3535x over previous
#include <cuda_runtime.h>
#include <cuda_bf16.h>
#include <math.h>

#define NSAMP 64
#define TLEN  512
#define DDIM  16
#define NDIAG 1023
#define BIGL  1.0e10f
#define LOG2E 1.4426950408889634f
#define LN2   0.6931471805599453f

// Scratch: D (pre-scaled by log2e) in diagonal-major layout: g_Ddiag[n][kk][ii]
__device__ float g_Ddiag[(size_t)NSAMP * 1024 * 512];   // 134 MB
__device__ float g_res[NSAMP];

__device__ __forceinline__ float ex2f(float x){ float y; asm("ex2.approx.ftz.f32 %0, %1;" : "=f"(y) : "f"(x)); return y; }
__device__ __forceinline__ float lg2f(float x){ float y; asm("lg2.approx.ftz.f32 %0, %1;" : "=f"(y) : "f"(x)); return y; }

// ---------------------------------------------------------------------------
// Kernel A: D[n,ii,jj] = ||X[n,ii]-Z[jj]||^2 * log2e, stored DIAGONAL-major.
// (unchanged — known good, ~65us)
// ---------------------------------------------------------------------------
__global__ void __launch_bounds__(512) compute_D_kernel(const float* __restrict__ X,
                                                        const float* __restrict__ Z)
{
    extern __shared__ float sm[];
    float* ts  = sm;                         // 64*514
    float* zsh = ts  + 64 * 514;             // 512*17
    float* z2s = zsh + 512 * 17;             // 512 (pre-scaled by LOG2E)
    float* xs  = z2s + 512;                  // 64*16

    const int n    = blockIdx.y;
    const int row0 = blockIdx.x * 64;
    const int tid  = threadIdx.x;
    const int w    = tid >> 5;
    const int lane = tid & 31;

    for (int i = tid; i < 512 * 16; i += 512)
        zsh[(i >> 4) * 17 + (i & 15)] = Z[i];
    const float* Xn = X + ((size_t)n * TLEN + row0) * DDIM;
    for (int i = tid; i < 64 * 16; i += 512)
        xs[i] = Xn[i];
    __syncthreads();

    {
        float s = 0.f;
        #pragma unroll
        for (int c = 0; c < 16; c++) { float v = zsh[tid * 17 + c]; s = fmaf(v, v, s); }
        z2s[tid] = s * LOG2E;
    }

    float xr[4][16], x2r[4];
    #pragma unroll
    for (int q = 0; q < 4; q++) {
        float s = 0.f;
        #pragma unroll
        for (int c = 0; c < 16; c++) {
            float v = xs[(w * 4 + q) * 16 + c];
            xr[q][c] = v; s = fmaf(v, v, s);
        }
        x2r[q] = s * LOG2E;
    }
    __syncthreads();

    #pragma unroll 1
    for (int t = 0; t < 16; t++) {
        const int jj = lane + 32 * t;
        float zr[16];
        #pragma unroll
        for (int c = 0; c < 16; c++) zr[c] = zsh[jj * 17 + c];
        const float z2v = z2s[jj];
        #pragma unroll
        for (int q = 0; q < 4; q++) {
            float acc = 0.f;
            #pragma unroll
            for (int c = 0; c < 16; c++) acc = fmaf(xr[q][c], zr[c], acc);
            ts[(w * 4 + q) * 514 + jj] = fmaxf(fmaf(acc, -2.0f * LOG2E, x2r[q] + z2v), 0.0f);
        }
    }
    __syncthreads();

    const size_t base = (size_t)n * (1024 * 512);
    for (int kkoff = w; kkoff < 575; kkoff += 16) {
        const int kk   = row0 + kkoff;
        const int iilo = max(row0, kk - 511);
        const int iihi = min(row0 + 63, kk);
        for (int ii = iilo + lane; ii <= iihi; ii += 32)
            g_Ddiag[base + (size_t)kk * 512 + ii] = ts[(ii - row0) * 514 + (kk - ii)];
    }
}

// ---------------------------------------------------------------------------
// Kernel B: log2-domain soft-DTW wavefront. 64 CTAs (1/sample), 128 threads
// (4 warps = 1/SMSP), 4 cells/thread. Register-resident prefetch ring:
// buffer index is a compile-time constant in every unrolled body.
// NOTE: macro local is kkq — NOT kk — to avoid self-initialization shadowing
// (the R6 bug: `const int kk = (kk);`).
// ---------------------------------------------------------------------------
#define PF 8

__global__ void __launch_bounds__(128) dp_kernel()
{
    const int n    = blockIdx.x;
    const int tid  = threadIdx.x;
    const int w    = tid >> 5;
    const int lane = tid & 31;

    __shared__ float sb[2][4];               // lane31-cell3 boundary, ping-pong
    if (tid < 8) (&sb[0][0])[tid] = BIGL;

    float rc0 = BIGL, rc1 = BIGL, rc2 = BIGL, rc3 = BIGL;
    float rd0 = BIGL, rd1 = BIGL, rd2 = BIGL, rd3 = BIGL;
    if (tid == 0) rd0 = 0.0f;                // corner R[0][0]

    const float4* __restrict__ Dn4 = (const float4*)(g_Ddiag + (size_t)n * (1024 * 512));
    float4 dbuf[PF];
    #pragma unroll
    for (int i = 0; i < PF; i++) dbuf[i] = Dn4[(size_t)i * 128 + tid];

    const int row0 = 4 * tid;
    __syncthreads();

#define DP_STEP(KK, D4)                                                        \
    {                                                                          \
        const int kkq = (KK);                                                  \
        float upsh = __shfl_up_sync(0xffffffffu, rc3, 1);                      \
        if (lane == 0) upsh = (w ? sb[kkq & 1][w - 1] : BIGL);                 \
        const float u0 = upsh, u1 = rc0, u2 = rc1, u3 = rc2;                   \
        {                                                                      \
            float m  = fminf(fminf(u0, rc0), rd0);                             \
            float Mx = fmaxf(fmaxf(u0, rc0), rd0);                             \
            float mid = ((u0 + rc0) + rd0) - m - Mx;                           \
            float s  = 1.0f + ex2f(m - mid) + ex2f(m - Mx);                    \
            float v  = ((D4).x + m) - lg2f(s);                                 \
            if ((unsigned)(kkq - (row0 + 0)) >= 512u) v = BIGL;                \
            rd0 = u0; rc0 = v;                                                 \
        }                                                                      \
        {                                                                      \
            float m  = fminf(fminf(u1, rc1), rd1);                             \
            float Mx = fmaxf(fmaxf(u1, rc1), rd1);                             \
            float mid = ((u1 + rc1) + rd1) - m - Mx;                           \
            float s  = 1.0f + ex2f(m - mid) + ex2f(m - Mx);                    \
            float v  = ((D4).y + m) - lg2f(s);                                 \
            if ((unsigned)(kkq - (row0 + 1)) >= 512u) v = BIGL;                \
            rd1 = u1; rc1 = v;                                                 \
        }                                                                      \
        {                                                                      \
            float m  = fminf(fminf(u2, rc2), rd2);                             \
            float Mx = fmaxf(fmaxf(u2, rc2), rd2);                             \
            float mid = ((u2 + rc2) + rd2) - m - Mx;                           \
            float s  = 1.0f + ex2f(m - mid) + ex2f(m - Mx);                    \
            float v  = ((D4).z + m) - lg2f(s);                                 \
            if ((unsigned)(kkq - (row0 + 2)) >= 512u) v = BIGL;                \
            rd2 = u2; rc2 = v;                                                 \
        }                                                                      \
        {                                                                      \
            float m  = fminf(fminf(u3, rc3), rd3);                             \
            float Mx = fmaxf(fmaxf(u3, rc3), rd3);                             \
            float mid = ((u3 + rc3) + rd3) - m - Mx;                           \
            float s  = 1.0f + ex2f(m - mid) + ex2f(m - Mx);                    \
            float v  = ((D4).w + m) - lg2f(s);                                 \
            if ((unsigned)(kkq - (row0 + 3)) >= 512u) v = BIGL;                \
            rd3 = u3; rc3 = v;                                                 \
        }                                                                      \
        if (lane == 31) sb[(kkq + 1) & 1][w] = rc3;                            \
    }

    // Main loop: 127 blocks of 8 diagonals; slot j == kk & 7 (block start % 8 == 0).
    #pragma unroll 1
    for (int base_kk = 0; base_kk < 1016; base_kk += 8) {
        #pragma unroll
        for (int j = 0; j < 8; j++) {
            const int cur = base_kk + j;
            DP_STEP(cur, dbuf[j]);
            if (cur + PF < NDIAG)                      // false only at cur=1015
                dbuf[j] = Dn4[(size_t)(cur + PF) * 128 + tid];
            __syncthreads();
        }
    }
    // Tail: kk = 1016..1022, slots 0..6.
    #pragma unroll
    for (int j = 0; j < 7; j++) {
        DP_STEP(1016 + j, dbuf[j]);
        __syncthreads();
    }
#undef DP_STEP

    if (tid == 127) g_res[n] = rc3 * LN2;    // row 511: R[T,T], back to ln units
}

// ---------------------------------------------------------------------------
// Kernel C: deterministic weighted reduction.
// ---------------------------------------------------------------------------
__global__ void reduce_kernel(const float* __restrict__ wts, float* __restrict__ out)
{
    __shared__ float s[64];
    const int tid = threadIdx.x;
    s[tid] = g_res[tid] * wts[tid];
    __syncthreads();
    #pragma unroll
    for (int off = 32; off > 0; off >>= 1) {
        if (tid < off) s[tid] += s[tid + off];
        __syncthreads();
    }
    if (tid == 0) out[0] = s[0];
}

// ---------------------------------------------------------------------------
extern "C" void kernel_launch(void* const* d_in, const int* in_sizes, int n_in,
                              void* d_out, int out_size)
{
    const float* X = nullptr; const float* wts = nullptr; const float* Z = nullptr;
    for (int i = 0; i < n_in; i++) {
        if      (in_sizes[i] == NSAMP)        wts = (const float*)d_in[i];
        else if (in_sizes[i] == TLEN * DDIM)  Z   = (const float*)d_in[i];
        else                                  X   = (const float*)d_in[i];
    }
    float* out = (float*)d_out;

    const int smemA = (64 * 514 + 512 * 17 + 512 + 64 * 16) * (int)sizeof(float); // 172544
    cudaFuncSetAttribute(compute_D_kernel, cudaFuncAttributeMaxDynamicSharedMemorySize, smemA);

    compute_D_kernel<<<dim3(8, NSAMP), 512, smemA>>>(X, Z);
    dp_kernel<<<NSAMP, 128>>>();
    reduce_kernel<<<1, 64>>>(wts, out);
}

// round 9
// speedup vs baseline: 3.5481x; 1.3735x over previous
#include <cuda_runtime.h>
#include <cuda_bf16.h>
#include <math.h>

#define NSAMP 64
#define TLEN  512
#define DDIM  16
#define NDIAG 1023
#define BIGL  1.0e10f
#define LOG2E 1.4426950408889634f
#define LN2   0.6931471805599453f

// Scratch: D (pre-scaled by log2e) in diagonal-major layout: g_Ddiag[n][kk][ii]
__device__ float g_Ddiag[(size_t)NSAMP * 1024 * 512];   // 134 MB
__device__ float g_res[NSAMP];

__device__ __forceinline__ float ex2f(float x){ float y; asm("ex2.approx.ftz.f32 %0, %1;" : "=f"(y) : "f"(x)); return y; }
__device__ __forceinline__ float lg2f(float x){ float y; asm("lg2.approx.ftz.f32 %0, %1;" : "=f"(y) : "f"(x)); return y; }

// ---------------------------------------------------------------------------
// Kernel A: D[n,ii,jj] = ||X[n,ii]-Z[jj]||^2 * log2e, stored DIAGONAL-major.
// (unchanged — known good, ~65us)
// ---------------------------------------------------------------------------
__global__ void __launch_bounds__(512) compute_D_kernel(const float* __restrict__ X,
                                                        const float* __restrict__ Z)
{
    extern __shared__ float sm[];
    float* ts  = sm;                         // 64*514
    float* zsh = ts  + 64 * 514;             // 512*17
    float* z2s = zsh + 512 * 17;             // 512 (pre-scaled by LOG2E)
    float* xs  = z2s + 512;                  // 64*16

    const int n    = blockIdx.y;
    const int row0 = blockIdx.x * 64;
    const int tid  = threadIdx.x;
    const int w    = tid >> 5;
    const int lane = tid & 31;

    for (int i = tid; i < 512 * 16; i += 512)
        zsh[(i >> 4) * 17 + (i & 15)] = Z[i];
    const float* Xn = X + ((size_t)n * TLEN + row0) * DDIM;
    for (int i = tid; i < 64 * 16; i += 512)
        xs[i] = Xn[i];
    __syncthreads();

    {
        float s = 0.f;
        #pragma unroll
        for (int c = 0; c < 16; c++) { float v = zsh[tid * 17 + c]; s = fmaf(v, v, s); }
        z2s[tid] = s * LOG2E;
    }

    float xr[4][16], x2r[4];
    #pragma unroll
    for (int q = 0; q < 4; q++) {
        float s = 0.f;
        #pragma unroll
        for (int c = 0; c < 16; c++) {
            float v = xs[(w * 4 + q) * 16 + c];
            xr[q][c] = v; s = fmaf(v, v, s);
        }
        x2r[q] = s * LOG2E;
    }
    __syncthreads();

    #pragma unroll 1
    for (int t = 0; t < 16; t++) {
        const int jj = lane + 32 * t;
        float zr[16];
        #pragma unroll
        for (int c = 0; c < 16; c++) zr[c] = zsh[jj * 17 + c];
        const float z2v = z2s[jj];
        #pragma unroll
        for (int q = 0; q < 4; q++) {
            float acc = 0.f;
            #pragma unroll
            for (int c = 0; c < 16; c++) acc = fmaf(xr[q][c], zr[c], acc);
            ts[(w * 4 + q) * 514 + jj] = fmaxf(fmaf(acc, -2.0f * LOG2E, x2r[q] + z2v), 0.0f);
        }
    }
    __syncthreads();

    const size_t base = (size_t)n * (1024 * 512);
    for (int kkoff = w; kkoff < 575; kkoff += 16) {
        const int kk   = row0 + kkoff;
        const int iilo = max(row0, kk - 511);
        const int iihi = min(row0 + 63, kk);
        for (int ii = iilo + lane; ii <= iihi; ii += 32)
            g_Ddiag[base + (size_t)kk * 512 + ii] = ts[(ii - row0) * 514 + (kk - ii)];
    }
}

// ---------------------------------------------------------------------------
// Kernel B: log2-domain soft-DTW wavefront, STAIRCASE schedule.
// Warp w runs 8 diagonals behind warp w-1: one __syncthreads per 8 diagonals.
// R8 bug fixed: warp 3's final phase executes one step past diag 1022
// (cur=1023) whose band mask overwrote rc3 — the result is now snapshotted
// at kkq==1022 into resv before that step can clobber it.
// ---------------------------------------------------------------------------
#define NPHASE 131   // warp 3 reaches diag 1022 at phase 130 (j=6)

__global__ void __launch_bounds__(128) dp_kernel()
{
    const int n    = blockIdx.x;
    const int tid  = threadIdx.x;
    const int w    = tid >> 5;
    const int lane = tid & 31;

    __shared__ float rings[5][32];     // warp w reads rings[w], writes rings[w+1]
    for (int i = tid; i < 5 * 32; i += 128) (&rings[0][0])[i] = BIGL;

    float rc0 = BIGL, rc1 = BIGL, rc2 = BIGL, rc3 = BIGL;
    float rd0 = BIGL, rd1 = BIGL, rd2 = BIGL, rd3 = BIGL;
    if (tid == 0) rd0 = 0.0f;          // corner R[0][0]
    float resv = BIGL;                 // snapshot of rc3 at diag 1022

    const float4* __restrict__ Dn4 = (const float4*)(g_Ddiag + (size_t)n * (1024 * 512));
    float4 dbuf[8];
    #pragma unroll
    for (int j = 0; j < 8; j++) {
        int idx = j - 8 * w; idx = idx < 0 ? 0 : idx;
        dbuf[j] = Dn4[(size_t)idx * 128 + tid];
    }

    const int row0 = 4 * tid;          // first of this thread's 4 rows
    float* ringr = &rings[w][0];       // read ring (warp 0 -> all-BIGL row)
    float* ringw = &rings[w + 1][0];   // write ring
    __syncthreads();

#define DP_STEP(KK, D4)                                                        \
    {                                                                          \
        const int kkq = (KK);                                                  \
        const float bval = ringr[(kkq - 1) & 31];   /* uniform LDS, off-chain */ \
        float upsh = __shfl_up_sync(0xffffffffu, rc3, 1);                      \
        const float u0 = (lane == 0) ? bval : upsh;                            \
        const float u1 = rc0, u2 = rc1, u3 = rc2;                              \
        {                                                                      \
            float m  = fminf(fminf(u0, rc0), rd0);                             \
            float Mx = fmaxf(fmaxf(u0, rc0), rd0);                             \
            float mid = ((u0 + rc0) + rd0) - m - Mx;                           \
            float s  = 1.0f + ex2f(m - mid) + ex2f(m - Mx);                    \
            float v  = ((D4).x + m) - lg2f(s);                                 \
            if ((unsigned)(kkq - (row0 + 0)) >= 512u) v = BIGL;                \
            rd0 = u0; rc0 = v;                                                 \
        }                                                                      \
        {                                                                      \
            float m  = fminf(fminf(u1, rc1), rd1);                             \
            float Mx = fmaxf(fmaxf(u1, rc1), rd1);                             \
            float mid = ((u1 + rc1) + rd1) - m - Mx;                           \
            float s  = 1.0f + ex2f(m - mid) + ex2f(m - Mx);                    \
            float v  = ((D4).y + m) - lg2f(s);                                 \
            if ((unsigned)(kkq - (row0 + 1)) >= 512u) v = BIGL;                \
            rd1 = u1; rc1 = v;                                                 \
        }                                                                      \
        {                                                                      \
            float m  = fminf(fminf(u2, rc2), rd2);                             \
            float Mx = fmaxf(fmaxf(u2, rc2), rd2);                             \
            float mid = ((u2 + rc2) + rd2) - m - Mx;                           \
            float s  = 1.0f + ex2f(m - mid) + ex2f(m - Mx);                    \
            float v  = ((D4).z + m) - lg2f(s);                                 \
            if ((unsigned)(kkq - (row0 + 2)) >= 512u) v = BIGL;                \
            rd2 = u2; rc2 = v;                                                 \
        }                                                                      \
        {                                                                      \
            float m  = fminf(fminf(u3, rc3), rd3);                             \
            float Mx = fmaxf(fmaxf(u3, rc3), rd3);                             \
            float mid = ((u3 + rc3) + rd3) - m - Mx;                           \
            float s  = 1.0f + ex2f(m - mid) + ex2f(m - Mx);                    \
            float v  = ((D4).w + m) - lg2f(s);                                 \
            if ((unsigned)(kkq - (row0 + 3)) >= 512u) v = BIGL;                \
            rd3 = u3; rc3 = v;                                                 \
        }                                                                      \
        if (kkq == NDIAG - 1) resv = rc3;          /* snapshot before overrun */ \
        if (lane == 31 && (unsigned)kkq < 1023u) ringw[kkq & 31] = rc3;        \
    }

    #pragma unroll 1
    for (int p = 0; p < NPHASE; ++p) {
        const int kwb = 8 * p - 8 * w;         // this warp's diag at j=0
        #pragma unroll
        for (int j = 0; j < 8; j++) {
            const int cur = kwb + j;
            DP_STEP(cur, dbuf[j]);
            int nid = cur + 8;                 // branchless clamped prefetch
            nid = nid < 0 ? 0 : (nid > 1022 ? 1022 : nid);
            dbuf[j] = Dn4[(size_t)nid * 128 + tid];
        }
        __syncthreads();
    }
#undef DP_STEP

    if (tid == 127) g_res[n] = resv * LN2;     // row 511 at diag 1022: R[T,T]
}

// ---------------------------------------------------------------------------
// Kernel C: deterministic weighted reduction.
// ---------------------------------------------------------------------------
__global__ void reduce_kernel(const float* __restrict__ wts, float* __restrict__ out)
{
    __shared__ float s[64];
    const int tid = threadIdx.x;
    s[tid] = g_res[tid] * wts[tid];
    __syncthreads();
    #pragma unroll
    for (int off = 32; off > 0; off >>= 1) {
        if (tid < off) s[tid] += s[tid + off];
        __syncthreads();
    }
    if (tid == 0) out[0] = s[0];
}

// ---------------------------------------------------------------------------
extern "C" void kernel_launch(void* const* d_in, const int* in_sizes, int n_in,
                              void* d_out, int out_size)
{
    const float* X = nullptr; const float* wts = nullptr; const float* Z = nullptr;
    for (int i = 0; i < n_in; i++) {
        if      (in_sizes[i] == NSAMP)        wts = (const float*)d_in[i];
        else if (in_sizes[i] == TLEN * DDIM)  Z   = (const float*)d_in[i];
        else                                  X   = (const float*)d_in[i];
    }
    float* out = (float*)d_out;

    const int smemA = (64 * 514 + 512 * 17 + 512 + 64 * 16) * (int)sizeof(float); // 172544
    cudaFuncSetAttribute(compute_D_kernel, cudaFuncAttributeMaxDynamicSharedMemorySize, smemA);

    compute_D_kernel<<<dim3(8, NSAMP), 512, smemA>>>(X, Z);
    dp_kernel<<<NSAMP, 128>>>();
    reduce_kernel<<<1, 64>>>(wts, out);
}